// round 12
// baseline (speedup 1.0000x reference)
#include <cuda_runtime.h>
#include <cuda_bf16.h>
#include <cstdint>

// Problem constants
#define R_TOTAL 24576   // B*T*N = 2*12*1024
#define DMODEL  128
#define NKEYS   1024
#define NHEADS  8

// ---------- helpers ----------
__device__ __forceinline__ float ex2(float x) {
    float y; asm("ex2.approx.f32 %0, %1;" : "=f"(y) : "f"(x)); return y;
}
// pack two floats to bf16x2: low half = first arg, high half = second arg
__device__ __forceinline__ uint32_t pkbf(float lo, float hi) {
    uint32_t d;
    asm("cvt.rn.bf16x2.f32 %0, %1, %2;" : "=r"(d) : "f"(hi), "f"(lo));
    return d;
}

// HMMA: mma.sync m16n8k16 bf16 (baseline PTX, works on sm_103)
__device__ __forceinline__ void mma_bf16(float* c, const uint32_t* a,
                                         uint32_t b0, uint32_t b1) {
    asm volatile(
        "mma.sync.aligned.m16n8k16.row.col.f32.bf16.bf16.f32 "
        "{%0,%1,%2,%3}, {%4,%5,%6,%7}, {%8,%9}, {%0,%1,%2,%3};"
        : "+f"(c[0]), "+f"(c[1]), "+f"(c[2]), "+f"(c[3])
        : "r"(a[0]), "r"(a[1]), "r"(a[2]), "r"(a[3]), "r"(b0), "r"(b1));
}

// split fp32 -> (hi, lo) bf16 pair
__device__ __forceinline__ void bsplit(float x, unsigned short& h, unsigned short& l) {
    __nv_bfloat16 bh = __float2bfloat16(x);
    __nv_bfloat16 bl = __float2bfloat16(x - __bfloat162float(bh));
    h = __bfloat16_as_ushort(bh);
    l = __bfloat16_as_ushort(bl);
}

// split a pair of floats into packed hi word + lo word
__device__ __forceinline__ void psplit(float p0, float p1, uint32_t& hw, uint32_t& lw) {
    hw = pkbf(p0, p1);
    float f0 = __uint_as_float(hw << 16);
    float f1 = __uint_as_float(hw & 0xffff0000u);
    lw = pkbf(p0 - f0, p1 - f1);
}

__device__ __forceinline__ void cp16(void* dst, const void* src) {
    uint32_t d = (uint32_t)__cvta_generic_to_shared(dst);
    asm volatile("cp.async.cg.shared.global [%0], [%1], 16;" :: "r"(d), "l"(src));
}
__device__ __forceinline__ void cp_commit() {
    asm volatile("cp.async.commit_group;");
}
template<int N> __device__ __forceinline__ void cp_wait() {
    asm volatile("cp.async.wait_group %0;" :: "n"(N));
}

// ---------- scratch (no cudaMalloc allowed) ----------
// Pre-split bf16 word arrays: [bth][n][8 words] (word = packed (hd, hd+1))
__device__ uint32_t g_qhi[R_TOTAL * 64], g_qlo[R_TOTAL * 64];
__device__ uint32_t g_khi[R_TOTAL * 64], g_klo[R_TOTAL * 64];
__device__ uint32_t g_vhi[R_TOTAL * 64], g_vlo[R_TOTAL * 64];
__device__ float    g_ao [R_TOTAL * DMODEL];       // attention out, row-major
// W pre-split per-chunk images: [which*4+chunk][row][16 words]
__device__ uint32_t g_whi[4 * 4 * 2048], g_wlo[4 * 4 * 2048];

// ============================================================================
// wsplit: one-time split of the 4 weight matrices into per-chunk hi/lo images.
// ============================================================================
__global__ __launch_bounds__(256) void wsplit_kernel(
    const float* __restrict__ W0, const float* __restrict__ W1,
    const float* __restrict__ W2, const float* __restrict__ W3)
{
    const int m = blockIdx.x;
    const float* W = (m == 0) ? W0 : (m == 1) ? W1 : (m == 2) ? W2 : W3;
    for (int widx = threadIdx.x; widx < 4 * 128 * 16; widx += 256) {
        int w = widx & 15;
        int rowc = widx >> 4;
        int row = rowc & 127;
        int chunk = rowc >> 7;
        int k = chunk * 32 + w * 2;
        unsigned short h0, l0, h1, l1;
        bsplit(W[row * 128 + k],     h0, l0);
        bsplit(W[row * 128 + k + 1], h1, l1);
        int o = (m * 4 + chunk) * 2048 + row * 16 + w;
        g_whi[o] = (uint32_t)h0 | ((uint32_t)h1 << 16);
        g_wlo[o] = (uint32_t)l0 | ((uint32_t)l1 << 16);
    }
}

// ============================================================================
// HMMA GEMM body. X converted in-kernel; W staged via cp.async of pre-split
// images. Output either fp32 row-major (+bias) or split-bf16 head-major
// (+bias, *scale) written to (outHi, outLo).
// ============================================================================
#define SPAD 20

__device__ __forceinline__ void gemm_hmma_body(
    const float* __restrict__ X,
    const uint32_t* __restrict__ whi, const uint32_t* __restrict__ wlo,
    const float* __restrict__ bias,
    float* __restrict__ outF, uint32_t* __restrict__ outHi,
    uint32_t* __restrict__ outLo, float scale, int row0)
{
    __shared__ uint32_t XsHi[128 * SPAD], XsLo[128 * SPAD];
    __shared__ uint32_t WsHi[128 * SPAD], WsLo[128 * SPAD];

    const int tid   = threadIdx.x;
    const int wid   = tid >> 5;
    const int lane  = tid & 31;
    const int g     = lane >> 2;
    const int t     = lane & 3;
    const int mwarp = wid & 3;
    const int nwarp = wid >> 2;

    float c[2][8][4];
    #pragma unroll
    for (int mt = 0; mt < 2; ++mt)
        #pragma unroll
        for (int nt = 0; nt < 8; ++nt)
            #pragma unroll
            for (int e = 0; e < 4; ++e) c[mt][nt][e] = 0.0f;

    for (int chunk = 0; chunk < 4; ++chunk) {
        const int k0 = chunk * 32;
        // ---- issue W copies (pre-split, no conversion) ----
        const uint32_t* whiC = whi + chunk * 2048;
        const uint32_t* wloC = wlo + chunk * 2048;
        #pragma unroll
        for (int i = 0; i < 2; ++i) {
            int idx = tid + i * 256;          // 0..511
            int row = idx >> 2, q4 = idx & 3;
            cp16((char*)WsHi + row * 80 + q4 * 16, whiC + row * 16 + q4 * 4);
            cp16((char*)WsLo + row * 80 + q4 * 16, wloC + row * 16 + q4 * 4);
        }
        cp_commit();

        // ---- convert X chunk (fp32 -> hi/lo) while W flies ----
        #pragma unroll
        for (int i = 0; i < 4; ++i) {
            int idx = tid + i * 256;
            int row = idx >> 3;
            int c4  = idx & 7;
            float4 v = *(const float4*)(X + (size_t)(row0 + row) * 128 + k0 + c4 * 4);
            unsigned short h0, l0, h1, l1, h2, l2, h3, l3;
            bsplit(v.x, h0, l0); bsplit(v.y, h1, l1);
            bsplit(v.z, h2, l2); bsplit(v.w, h3, l3);
            int wi = row * SPAD + c4 * 2;
            XsHi[wi]     = (uint32_t)h0 | ((uint32_t)h1 << 16);
            XsHi[wi + 1] = (uint32_t)h2 | ((uint32_t)h3 << 16);
            XsLo[wi]     = (uint32_t)l0 | ((uint32_t)l1 << 16);
            XsLo[wi + 1] = (uint32_t)l2 | ((uint32_t)l3 << 16);
        }
        cp_wait<0>();
        __syncthreads();

        #pragma unroll
        for (int ks = 0; ks < 2; ++ks) {
            const int kw = ks * 8;
            uint32_t ahi[2][4], alo[2][4];
            #pragma unroll
            for (int mt = 0; mt < 2; ++mt) {
                int r0 = (mwarp * 32 + mt * 16 + g) * SPAD + kw + t;
                int r8 = r0 + 8 * SPAD;
                ahi[mt][0] = XsHi[r0];     ahi[mt][1] = XsHi[r8];
                ahi[mt][2] = XsHi[r0 + 4]; ahi[mt][3] = XsHi[r8 + 4];
                alo[mt][0] = XsLo[r0];     alo[mt][1] = XsLo[r8];
                alo[mt][2] = XsLo[r0 + 4]; alo[mt][3] = XsLo[r8 + 4];
            }
            #pragma unroll
            for (int nt = 0; nt < 8; ++nt) {
                int b = (nwarp * 64 + nt * 8 + g) * SPAD + kw + t;
                uint32_t bh0 = WsHi[b], bh1 = WsHi[b + 4];
                uint32_t bl0 = WsLo[b], bl1 = WsLo[b + 4];
                #pragma unroll
                for (int mt = 0; mt < 2; ++mt) {
                    mma_bf16(c[mt][nt], ahi[mt], bh0, bh1);
                    mma_bf16(c[mt][nt], ahi[mt], bl0, bl1);
                    mma_bf16(c[mt][nt], alo[mt], bh0, bh1);
                }
            }
        }
        __syncthreads();
    }

    // ---- epilogue ----
    #pragma unroll
    for (int mt = 0; mt < 2; ++mt) {
        int rA = row0 + mwarp * 32 + mt * 16 + g;
        int rB = rA + 8;
        #pragma unroll
        for (int nt = 0; nt < 8; ++nt) {
            int j0 = nwarp * 64 + nt * 8 + t * 2;
            float b0 = bias[j0], b1 = bias[j0 + 1];
            float oA0 = c[mt][nt][0] + b0, oA1 = c[mt][nt][1] + b1;
            float oB0 = c[mt][nt][2] + b0, oB1 = c[mt][nt][3] + b1;
            if (outF) {
                *(float2*)(outF + (size_t)rA * 128 + j0) = make_float2(oA0, oA1);
                *(float2*)(outF + (size_t)rB * 128 + j0) = make_float2(oB0, oB1);
            } else {
                int h = j0 >> 4, hw2 = (j0 & 15) >> 1;
                int btA = rA >> 10, nA = rA & 1023;
                int btB = rB >> 10, nB = rB & 1023;
                uint32_t hA, lA, hB, lB;
                psplit(oA0 * scale, oA1 * scale, hA, lA);
                psplit(oB0 * scale, oB1 * scale, hB, lB);
                size_t wA = (((size_t)(btA * NHEADS + h)) << 13) + (nA << 3) + hw2;
                size_t wB = (((size_t)(btB * NHEADS + h)) << 13) + (nB << 3) + hw2;
                outHi[wA] = hA; outLo[wA] = lA;
                outHi[wB] = hB; outLo[wB] = lB;
            }
        }
    }
}

__global__ __launch_bounds__(256, 2) void gemm_qkv(
    const float* __restrict__ Xq, const float* __restrict__ Xk,
    const float* __restrict__ Xv,
    const float* __restrict__ bq, const float* __restrict__ bk,
    const float* __restrict__ bv)
{
    const int which = blockIdx.y;
    const float sc = 0.25f * 1.4426950408889634f;
    const float* X = (which == 0) ? Xq : (which == 1) ? Xk : Xv;
    const float* b = (which == 0) ? bq : (which == 1) ? bk : bv;
    uint32_t* oh = (which == 0) ? g_qhi : (which == 1) ? g_khi : g_vhi;
    uint32_t* ol = (which == 0) ? g_qlo : (which == 1) ? g_klo : g_vlo;
    float scale = (which == 0) ? sc : 1.0f;
    gemm_hmma_body(X, g_whi + which * 4 * 2048, g_wlo + which * 4 * 2048,
                   b, nullptr, oh, ol, scale, blockIdx.x * 128);
}

__global__ __launch_bounds__(256, 2) void gemm_o(
    const float* __restrict__ X, const float* __restrict__ bias,
    float* __restrict__ out)
{
    gemm_hmma_body(X, g_whi + 3 * 4 * 2048, g_wlo + 3 * 4 * 2048,
                   bias, out, nullptr, nullptr, 1.0f, blockIdx.x * 128);
}

// ============================================================================
// Attention v8: HMMA flash-attention on PRE-SPLIT inputs (zero conversions).
// K staged via double-buffered cp.async; V transposed via u16 reg scatter.
// Grid (8, 192); 256 thr / 8 warps; warp owns 16 query rows.
// ============================================================================
#define CK 64
#define NCHUNK (NKEYS / CK)
#define KSTRIDE 12       // words per K row (8 used + 4 pad)
#define VSTRIDE 72       // u16 per Vt row (64 used + 8 pad)

__global__ __launch_bounds__(256, 2) void attn_kernel(float* __restrict__ Oc)
{
    __shared__ uint32_t Kst[2][2][CK * KSTRIDE];  // [buf][hi/lo]
    __shared__ unsigned short VtHi[16 * VSTRIDE], VtLo[16 * VSTRIDE];

    const int tid  = threadIdx.x;
    const int wid  = tid >> 5;
    const int lane = tid & 31;
    const int g    = lane >> 2;
    const int t    = lane & 3;

    const int qt  = blockIdx.x;
    const int bth = blockIdx.y;
    const int bt  = bth >> 3, h = bth & 7;

    // ---- Q fragments: direct word loads (pre-scaled, pre-split) ----
    const int rA = qt * 128 + wid * 16 + g;
    const uint32_t* qhiW = g_qhi + (size_t)bth * 8192 + rA * 8;
    const uint32_t* qloW = g_qlo + (size_t)bth * 8192 + rA * 8;
    uint32_t aq_hi[4], aq_lo[4];
    aq_hi[0] = qhiW[t];      aq_hi[1] = qhiW[64 + t];
    aq_hi[2] = qhiW[t + 4];  aq_hi[3] = qhiW[64 + t + 4];
    aq_lo[0] = qloW[t];      aq_lo[1] = qloW[64 + t];
    aq_lo[2] = qloW[t + 4];  aq_lo[3] = qloW[64 + t + 4];

    // ---- staging thread roles ----
    const int kt2   = tid & 127;
    const int ki    = kt2 >> 1;            // key row in chunk
    const int khalf = kt2 & 1;             // 16B half of the hi/lo row
    const uint32_t* ksrc = ((tid < 128) ? g_khi : g_klo) + (size_t)bth * 8192;
    const int vrow  = tid >> 2;            // key row for V scatter
    const int vs    = tid & 3;             // 4-col group
    const uint32_t* vhiW = g_vhi + (size_t)bth * 8192;
    const uint32_t* vloW = g_vlo + (size_t)bth * 8192;

    // ---- prologue: K chunk 0 -> buf 0; V chunk 0 -> regs ----
    {
        const uint32_t* src = ksrc + (ki * 8 + khalf * 4);
        char* dst = (char*)Kst[0][tid < 128 ? 0 : 1] + ki * 48 + khalf * 16;
        cp16(dst, src);
        cp_commit();
    }
    uint2 vh_r = *(const uint2*)(vhiW + vrow * 8 + vs * 2);
    uint2 vl_r = *(const uint2*)(vloW + vrow * 8 + vs * 2);

    float o[2][4];
    #pragma unroll
    for (int j = 0; j < 2; ++j)
        #pragma unroll
        for (int e = 0; e < 4; ++e) o[j][e] = 0.0f;
    float rsA = 0.0f, rsB = 0.0f;

    #pragma unroll 1
    for (int cix = 0; cix < NCHUNK; ++cix) {
        if (cix) __syncthreads();       // previous compute done
        cp_wait<0>();                   // K(cix) landed in buf

        // ---- scatter V(cix) transposed (pure moves, no cvt) ----
        {
            int c0 = vs * 4;
            VtHi[(c0 + 0) * VSTRIDE + vrow] = (unsigned short)(vh_r.x);
            VtHi[(c0 + 1) * VSTRIDE + vrow] = (unsigned short)(vh_r.x >> 16);
            VtHi[(c0 + 2) * VSTRIDE + vrow] = (unsigned short)(vh_r.y);
            VtHi[(c0 + 3) * VSTRIDE + vrow] = (unsigned short)(vh_r.y >> 16);
            VtLo[(c0 + 0) * VSTRIDE + vrow] = (unsigned short)(vl_r.x);
            VtLo[(c0 + 1) * VSTRIDE + vrow] = (unsigned short)(vl_r.x >> 16);
            VtLo[(c0 + 2) * VSTRIDE + vrow] = (unsigned short)(vl_r.y);
            VtLo[(c0 + 3) * VSTRIDE + vrow] = (unsigned short)(vl_r.y >> 16);
        }
        __syncthreads();

        const int buf = cix & 1;
        // ---- issue K(cix+1) into alt buffer; prefetch V(cix+1) regs ----
        if (cix + 1 < NCHUNK) {
            const uint32_t* src = ksrc + ((cix + 1) * CK + ki) * 8 + khalf * 4;
            char* dst = (char*)Kst[buf ^ 1][tid < 128 ? 0 : 1] + ki * 48 + khalf * 16;
            cp16(dst, src);
            cp_commit();
            vh_r = *(const uint2*)(vhiW + ((cix + 1) * CK + vrow) * 8 + vs * 2);
            vl_r = *(const uint2*)(vloW + ((cix + 1) * CK + vrow) * 8 + vs * 2);
        }

        const uint32_t* Khi = Kst[buf][0];
        const uint32_t* Klo = Kst[buf][1];

        // ---- S = Q·K^T ----
        float s[8][4];
        #pragma unroll
        for (int i = 0; i < 8; ++i) {
            s[i][0] = 0.0f; s[i][1] = 0.0f; s[i][2] = 0.0f; s[i][3] = 0.0f;
            int b = (8 * i + g) * KSTRIDE + t;
            uint32_t bh0 = Khi[b], bh1 = Khi[b + 4];
            uint32_t bl0 = Klo[b], bl1 = Klo[b + 4];
            mma_bf16(s[i], aq_hi, bh0, bh1);
            mma_bf16(s[i], aq_hi, bl0, bl1);
            mma_bf16(s[i], aq_lo, bh0, bh1);
        }

        // ---- softmax (ex2) + PV, interleaved per k16-step ----
        const uint32_t* VtHiW = (const uint32_t*)VtHi;
        const uint32_t* VtLoW = (const uint32_t*)VtLo;
        #pragma unroll
        for (int ks = 0; ks < 4; ++ks) {
            uint32_t ap_hi[4], ap_lo[4];
            #pragma unroll
            for (int half = 0; half < 2; ++half) {
                float* cc = s[2 * ks + half];
                float p0 = ex2(cc[0]), p1 = ex2(cc[1]);
                float p2 = ex2(cc[2]), p3 = ex2(cc[3]);
                rsA += p0 + p1;
                rsB += p2 + p3;
                psplit(p0, p1, ap_hi[2 * half],     ap_lo[2 * half]);
                psplit(p2, p3, ap_hi[2 * half + 1], ap_lo[2 * half + 1]);
            }
            #pragma unroll
            for (int j = 0; j < 2; ++j) {
                int b = (8 * j + g) * (VSTRIDE / 2) + 8 * ks + t;
                uint32_t bh0 = VtHiW[b], bh1 = VtHiW[b + 4];
                uint32_t bl0 = VtLoW[b], bl1 = VtLoW[b + 4];
                mma_bf16(o[j], ap_hi, bh0, bh1);
                mma_bf16(o[j], ap_lo, bh0, bh1);
                mma_bf16(o[j], ap_hi, bl0, bl1);
            }
        }
    }

    // ---- denominators + write O (row-major for gemm_o) ----
    rsA += __shfl_xor_sync(0xffffffffu, rsA, 1);
    rsA += __shfl_xor_sync(0xffffffffu, rsA, 2);
    rsB += __shfl_xor_sync(0xffffffffu, rsB, 1);
    rsB += __shfl_xor_sync(0xffffffffu, rsB, 2);
    const float invA = 1.0f / rsA;
    const float invB = 1.0f / rsB;

    const int rB = rA + 8;
    #pragma unroll
    for (int j = 0; j < 2; ++j) {
        int col = h * 16 + 8 * j + 2 * t;
        float2 oA = { o[j][0] * invA, o[j][1] * invA };
        float2 oB = { o[j][2] * invB, o[j][3] * invB };
        *(float2*)(Oc + ((size_t)((bt << 10) | rA)) * 128 + col) = oA;
        *(float2*)(Oc + ((size_t)((bt << 10) | rB)) * 128 + col) = oB;
    }
}

// ============================================================================
extern "C" void kernel_launch(void* const* d_in, const int* in_sizes, int n_in,
                              void* d_out, int out_size) {
    const float* query = (const float*)d_in[0];
    const float* key   = (const float*)d_in[1];
    const float* value = (const float*)d_in[2];
    const float* Wq    = (const float*)d_in[3];
    const float* bq    = (const float*)d_in[4];
    const float* Wk    = (const float*)d_in[5];
    const float* bk    = (const float*)d_in[6];
    const float* Wv    = (const float*)d_in[7];
    const float* bv    = (const float*)d_in[8];
    const float* Wo    = (const float*)d_in[9];
    const float* bo    = (const float*)d_in[10];
    float* out = (float*)d_out;

    float* ao;
    cudaGetSymbolAddress((void**)&ao, g_ao);

    wsplit_kernel<<<4, 256>>>(Wq, Wk, Wv, Wo);
    gemm_qkv<<<dim3(192, 3), 256>>>(query, key, value, bq, bk, bv);
    attn_kernel<<<dim3(8, 192), 256>>>(ao);
    gemm_o<<<192, 256>>>(ao, bo, out);
}

// round 16
// speedup vs baseline: 1.5311x; 1.5311x over previous
#include <cuda_runtime.h>
#include <cuda_bf16.h>
#include <cstdint>

// Problem constants
#define R_TOTAL 24576   // B*T*N = 2*12*1024
#define DMODEL  128
#define NKEYS   1024
#define NHEADS  8

// ---------- helpers ----------
__device__ __forceinline__ float ex2(float x) {
    float y; asm("ex2.approx.f32 %0, %1;" : "=f"(y) : "f"(x)); return y;
}
// pack two floats to bf16x2: low half = first arg, high half = second arg
__device__ __forceinline__ uint32_t pkbf(float lo, float hi) {
    uint32_t d;
    asm("cvt.rn.bf16x2.f32 %0, %1, %2;" : "=r"(d) : "f"(hi), "f"(lo));
    return d;
}

// HMMA: mma.sync m16n8k16 bf16 (baseline PTX, works on sm_103)
__device__ __forceinline__ void mma_bf16(float* c, const uint32_t* a,
                                         uint32_t b0, uint32_t b1) {
    asm volatile(
        "mma.sync.aligned.m16n8k16.row.col.f32.bf16.bf16.f32 "
        "{%0,%1,%2,%3}, {%4,%5,%6,%7}, {%8,%9}, {%0,%1,%2,%3};"
        : "+f"(c[0]), "+f"(c[1]), "+f"(c[2]), "+f"(c[3])
        : "r"(a[0]), "r"(a[1]), "r"(a[2]), "r"(a[3]), "r"(b0), "r"(b1));
}

// split fp32 -> (hi, lo) bf16 pair
__device__ __forceinline__ void bsplit(float x, unsigned short& h, unsigned short& l) {
    __nv_bfloat16 bh = __float2bfloat16(x);
    __nv_bfloat16 bl = __float2bfloat16(x - __bfloat162float(bh));
    h = __bfloat16_as_ushort(bh);
    l = __bfloat16_as_ushort(bl);
}

// ---------- scratch (no cudaMalloc allowed) ----------
__device__ float g_qh[R_TOTAL * DMODEL];   // head-major (bt,h,n,hd)
__device__ float g_kh[R_TOTAL * DMODEL];
__device__ float g_vh[R_TOTAL * DMODEL];
__device__ float g_ao[R_TOTAL * DMODEL];   // attention out, row-major (r, d)
__device__ float g_sumv[192 * 16];         // per (bth, hd): sum_n V[n][hd]

// ============================================================================
// HMMA projection GEMM (round-10 PROVEN 3-term version):
// out[r,j] = X[r,:]·W[j,:] + bias[j]; split-bf16 Ahi·Bhi + Ahi·Blo + Alo·Bhi.
// 128x128 tile/CTA, 8 warps 4(m)x2(n).
// ============================================================================
#define SPAD 20

__device__ __forceinline__ void gemm_hmma_body(
    const float* __restrict__ X, const float* __restrict__ W,
    const float* __restrict__ bias, float* __restrict__ out,
    int row0, int headmajor)
{
    __shared__ uint32_t XsHi[128 * SPAD], XsLo[128 * SPAD];
    __shared__ uint32_t WsHi[128 * SPAD], WsLo[128 * SPAD];

    const int tid   = threadIdx.x;
    const int wid   = tid >> 5;
    const int lane  = tid & 31;
    const int g     = lane >> 2;
    const int t     = lane & 3;
    const int mwarp = wid & 3;
    const int nwarp = wid >> 2;

    float c[2][8][4];
    #pragma unroll
    for (int mt = 0; mt < 2; ++mt)
        #pragma unroll
        for (int nt = 0; nt < 8; ++nt)
            #pragma unroll
            for (int e = 0; e < 4; ++e) c[mt][nt][e] = 0.0f;

    for (int chunk = 0; chunk < 4; ++chunk) {
        const int k0 = chunk * 32;
        #pragma unroll
        for (int i = 0; i < 4; ++i) {
            int idx = tid + i * 256;
            int row = idx >> 3;
            int c4  = idx & 7;
            float4 v = *(const float4*)(X + (size_t)(row0 + row) * 128 + k0 + c4 * 4);
            unsigned short h0, l0, h1, l1, h2, l2, h3, l3;
            bsplit(v.x, h0, l0); bsplit(v.y, h1, l1);
            bsplit(v.z, h2, l2); bsplit(v.w, h3, l3);
            int wi = row * SPAD + c4 * 2;
            XsHi[wi]     = (uint32_t)h0 | ((uint32_t)h1 << 16);
            XsHi[wi + 1] = (uint32_t)h2 | ((uint32_t)h3 << 16);
            XsLo[wi]     = (uint32_t)l0 | ((uint32_t)l1 << 16);
            XsLo[wi + 1] = (uint32_t)l2 | ((uint32_t)l3 << 16);

            float4 wv = *(const float4*)(W + (size_t)row * 128 + k0 + c4 * 4);
            bsplit(wv.x, h0, l0); bsplit(wv.y, h1, l1);
            bsplit(wv.z, h2, l2); bsplit(wv.w, h3, l3);
            WsHi[wi]     = (uint32_t)h0 | ((uint32_t)h1 << 16);
            WsHi[wi + 1] = (uint32_t)h2 | ((uint32_t)h3 << 16);
            WsLo[wi]     = (uint32_t)l0 | ((uint32_t)l1 << 16);
            WsLo[wi + 1] = (uint32_t)l2 | ((uint32_t)l3 << 16);
        }
        __syncthreads();

        #pragma unroll
        for (int ks = 0; ks < 2; ++ks) {
            const int kw = ks * 8;
            uint32_t ahi[2][4], alo[2][4];
            #pragma unroll
            for (int mt = 0; mt < 2; ++mt) {
                int r0 = (mwarp * 32 + mt * 16 + g) * SPAD + kw + t;
                int r8 = r0 + 8 * SPAD;
                ahi[mt][0] = XsHi[r0];     ahi[mt][1] = XsHi[r8];
                ahi[mt][2] = XsHi[r0 + 4]; ahi[mt][3] = XsHi[r8 + 4];
                alo[mt][0] = XsLo[r0];     alo[mt][1] = XsLo[r8];
                alo[mt][2] = XsLo[r0 + 4]; alo[mt][3] = XsLo[r8 + 4];
            }
            #pragma unroll
            for (int nt = 0; nt < 8; ++nt) {
                int b = (nwarp * 64 + nt * 8 + g) * SPAD + kw + t;
                uint32_t bh0 = WsHi[b], bh1 = WsHi[b + 4];
                uint32_t bl0 = WsLo[b], bl1 = WsLo[b + 4];
                #pragma unroll
                for (int mt = 0; mt < 2; ++mt) {
                    mma_bf16(c[mt][nt], ahi[mt], bh0, bh1);
                    mma_bf16(c[mt][nt], ahi[mt], bl0, bl1);
                    mma_bf16(c[mt][nt], alo[mt], bh0, bh1);
                }
            }
        }
        __syncthreads();
    }

    #pragma unroll
    for (int mt = 0; mt < 2; ++mt) {
        int rA = row0 + mwarp * 32 + mt * 16 + g;
        int rB = rA + 8;
        #pragma unroll
        for (int nt = 0; nt < 8; ++nt) {
            int j0 = nwarp * 64 + nt * 8 + t * 2;
            float b0 = bias[j0], b1 = bias[j0 + 1];
            float2 oA = { c[mt][nt][0] + b0, c[mt][nt][1] + b1 };
            float2 oB = { c[mt][nt][2] + b0, c[mt][nt][3] + b1 };
            if (headmajor) {
                int h = j0 >> 4, hd = j0 & 15;
                int btA = rA >> 10, nA = rA & 1023;
                int btB = rB >> 10, nB = rB & 1023;
                *(float2*)(out + (((size_t)(btA * NHEADS + h)) << 14) + (nA << 4) + hd) = oA;
                *(float2*)(out + (((size_t)(btB * NHEADS + h)) << 14) + (nB << 4) + hd) = oB;
            } else {
                *(float2*)(out + (size_t)rA * 128 + j0) = oA;
                *(float2*)(out + (size_t)rB * 128 + j0) = oB;
            }
        }
    }
}

__global__ __launch_bounds__(256, 2) void gemm_qkv(
    const float* __restrict__ Xq, const float* __restrict__ Xk,
    const float* __restrict__ Xv,
    const float* __restrict__ Wq, const float* __restrict__ Wk,
    const float* __restrict__ Wv,
    const float* __restrict__ bq, const float* __restrict__ bk,
    const float* __restrict__ bv,
    float* __restrict__ oq, float* __restrict__ ok, float* __restrict__ ov)
{
    const int which = blockIdx.y;
    const float* X = (which == 0) ? Xq : (which == 1) ? Xk : Xv;
    const float* W = (which == 0) ? Wq : (which == 1) ? Wk : Wv;
    const float* b = (which == 0) ? bq : (which == 1) ? bk : bv;
    float*       o = (which == 0) ? oq : (which == 1) ? ok : ov;
    gemm_hmma_body(X, W, b, o, blockIdx.x * 128, 1);
}

__global__ __launch_bounds__(256, 2) void gemm_o(
    const float* __restrict__ X, const float* __restrict__ W,
    const float* __restrict__ bias, float* __restrict__ out)
{
    gemm_hmma_body(X, W, bias, out, blockIdx.x * 128, 0);
}

// ============================================================================
// sumv: g_sumv[bth][hd] = sum over all 1024 keys of V[bth][n][hd] (fp32 exact).
// ============================================================================
__global__ __launch_bounds__(256) void sumv_kernel(const float* __restrict__ Vh)
{
    __shared__ float sm[16][17];
    const int tid = threadIdx.x;
    const int seg = tid >> 4;
    const int hd  = tid & 15;
    const float* Vg = Vh + (size_t)blockIdx.x * 16384;
    float s = 0.0f;
    #pragma unroll 4
    for (int n = 0; n < 64; ++n)
        s += Vg[((seg * 64 + n) << 4) + hd];
    sm[seg][hd] = s;
    __syncthreads();
    if (tid < 16) {
        float tot = 0.0f;
        #pragma unroll
        for (int ss = 0; ss < 16; ++ss) tot += sm[ss][tid];
        g_sumv[blockIdx.x * 16 + tid] = tot;
    }
}

// ============================================================================
// Attention v10: single-mma HMMA flash-attention (weight-path errors are
// sqrt(N)-suppressed; value path protected by exact fp32 SumV):
//   S  = Qhi·Khi            (1 mma/tile; dS ~ 2e-4 -> dO/O ~ 1.4e-4)
//   p' = 2^s - 1  (|p'| ~ 0.05), P' single bf16
//   O  = (SumV + P'·Vhi) / (1024 + sum p')
// Grid (8,192); 256 thr / 8 warps; warp owns 16 query rows.
// ============================================================================
#define CK 64
#define NCHUNK (NKEYS / CK)
#define KSTRIDE 12       // words per K row (8 used + 4 pad)
#define VSTRIDE 72       // u16 per Vt row (64 used + 8 pad)

__global__ __launch_bounds__(256, 2) void attn_kernel(
    const float* __restrict__ Qh, const float* __restrict__ Kh,
    const float* __restrict__ Vh, float* __restrict__ Oc)
{
    __shared__ uint32_t Ksm[CK * KSTRIDE];
    __shared__ unsigned short Vt[16 * VSTRIDE];

    const int tid  = threadIdx.x;
    const int wid  = tid >> 5;
    const int lane = tid & 31;
    const int g    = lane >> 2;
    const int t    = lane & 3;

    const int qt  = blockIdx.x;
    const int bth = blockIdx.y;
    const int bt  = bth >> 3, h = bth & 7;

    const float* Qg = Qh + (size_t)bth * 16384;
    const float* Kg = Kh + (size_t)bth * 16384;
    const float* Vg = Vh + (size_t)bth * 16384;

    // ---- Q fragment (bf16), prescaled by 0.25*log2(e) ----
    const float sc = 0.25f * 1.4426950408889634f;
    const int rA = qt * 128 + wid * 16 + g;
    const int rB = rA + 8;
    uint32_t aq[4];
    {
        float2 xA0 = *(const float2*)(Qg + rA * 16 + 2 * t);
        float2 xB0 = *(const float2*)(Qg + rB * 16 + 2 * t);
        float2 xA1 = *(const float2*)(Qg + rA * 16 + 2 * t + 8);
        float2 xB1 = *(const float2*)(Qg + rB * 16 + 2 * t + 8);
        aq[0] = pkbf(xA0.x * sc, xA0.y * sc);
        aq[1] = pkbf(xB0.x * sc, xB0.y * sc);
        aq[2] = pkbf(xA1.x * sc, xA1.y * sc);
        aq[3] = pkbf(xB1.x * sc, xB1.y * sc);
    }

    float o[2][4];
    #pragma unroll
    for (int j = 0; j < 2; ++j)
        #pragma unroll
        for (int e = 0; e < 4; ++e) o[j][e] = 0.0f;
    float rsA = 0.0f, rsB = 0.0f;   // accumulate p' = p - 1

    // staging roles: thread -> one float4 of K and one of V per chunk
    const int srow = tid >> 2;       // key row in chunk
    const int sc4  = tid & 3;        // float4 slot

    // preload chunk 0
    float4 kreg = *(const float4*)(Kg + tid * 4);
    float4 vreg = *(const float4*)(Vg + tid * 4);

    #pragma unroll 1
    for (int cix = 0; cix < NCHUNK; ++cix) {
        if (cix) __syncthreads();

        // ---- stage K (bf16, row-major): 2 pkbf, no split ----
        {
            int wi = srow * KSTRIDE + sc4 * 2;
            Ksm[wi]     = pkbf(kreg.x, kreg.y);
            Ksm[wi + 1] = pkbf(kreg.z, kreg.w);
        }
        // ---- stage V transposed (bf16): 4 cvt ----
        {
            float vs[4] = { vreg.x, vreg.y, vreg.z, vreg.w };
            #pragma unroll
            for (int e = 0; e < 4; ++e) {
                int col = sc4 * 4 + e;
                Vt[col * VSTRIDE + srow] =
                    __bfloat16_as_ushort(__float2bfloat16(vs[e]));
            }
        }
        __syncthreads();

        // prefetch next chunk
        if (cix + 1 < NCHUNK) {
            kreg = *(const float4*)(Kg + (cix + 1) * CK * 16 + tid * 4);
            vreg = *(const float4*)(Vg + (cix + 1) * CK * 16 + tid * 4);
        }

        // ---- S = Qhi·Khi (single mma per 8-key tile) ----
        float s[8][4];
        #pragma unroll
        for (int i = 0; i < 8; ++i) {
            s[i][0] = 0.0f; s[i][1] = 0.0f; s[i][2] = 0.0f; s[i][3] = 0.0f;
            int b = (8 * i + g) * KSTRIDE + t;
            mma_bf16(s[i], aq, Ksm[b], Ksm[b + 4]);
        }

        // ---- centered softmax + PV (single mma per tile) ----
        const uint32_t* VtW = (const uint32_t*)Vt;
        #pragma unroll
        for (int ks = 0; ks < 4; ++ks) {
            uint32_t ap[4];
            #pragma unroll
            for (int half = 0; half < 2; ++half) {
                float* cc = s[2 * ks + half];
                float p0 = ex2(cc[0]) - 1.0f, p1 = ex2(cc[1]) - 1.0f;
                float p2 = ex2(cc[2]) - 1.0f, p3 = ex2(cc[3]) - 1.0f;
                rsA += p0 + p1;
                rsB += p2 + p3;
                ap[2 * half]     = pkbf(p0, p1);
                ap[2 * half + 1] = pkbf(p2, p3);
            }
            #pragma unroll
            for (int j = 0; j < 2; ++j) {
                int b = (8 * j + g) * (VSTRIDE / 2) + 8 * ks + t;
                mma_bf16(o[j], ap, VtW[b], VtW[b + 4]);
            }
        }
    }

    // ---- denominators: sum p = 1024 + sum p' ----
    rsA += __shfl_xor_sync(0xffffffffu, rsA, 1);
    rsA += __shfl_xor_sync(0xffffffffu, rsA, 2);
    rsB += __shfl_xor_sync(0xffffffffu, rsB, 1);
    rsB += __shfl_xor_sync(0xffffffffu, rsB, 2);
    const float invA = 1.0f / (1024.0f + rsA);
    const float invB = 1.0f / (1024.0f + rsB);

    // ---- O = (SumV + o) * inv, row-major for gemm_o ----
    const float* sv = g_sumv + bth * 16;
    #pragma unroll
    for (int j = 0; j < 2; ++j) {
        int hc = 8 * j + 2 * t;
        float sv0 = sv[hc], sv1 = sv[hc + 1];
        int col = h * 16 + hc;
        float2 oA = { (sv0 + o[j][0]) * invA, (sv1 + o[j][1]) * invA };
        float2 oB = { (sv0 + o[j][2]) * invB, (sv1 + o[j][3]) * invB };
        *(float2*)(Oc + ((size_t)((bt << 10) | rA)) * 128 + col) = oA;
        *(float2*)(Oc + ((size_t)((bt << 10) | rB)) * 128 + col) = oB;
    }
}

// ============================================================================
extern "C" void kernel_launch(void* const* d_in, const int* in_sizes, int n_in,
                              void* d_out, int out_size) {
    const float* query = (const float*)d_in[0];
    const float* key   = (const float*)d_in[1];
    const float* value = (const float*)d_in[2];
    const float* Wq    = (const float*)d_in[3];
    const float* bq    = (const float*)d_in[4];
    const float* Wk    = (const float*)d_in[5];
    const float* bk    = (const float*)d_in[6];
    const float* Wv    = (const float*)d_in[7];
    const float* bv    = (const float*)d_in[8];
    const float* Wo    = (const float*)d_in[9];
    const float* bo    = (const float*)d_in[10];
    float* out = (float*)d_out;

    float *qh, *kh, *vh, *ao;
    cudaGetSymbolAddress((void**)&qh, g_qh);
    cudaGetSymbolAddress((void**)&kh, g_kh);
    cudaGetSymbolAddress((void**)&vh, g_vh);
    cudaGetSymbolAddress((void**)&ao, g_ao);

    gemm_qkv<<<dim3(192, 3), 256>>>(query, key, value,
                                    Wq, Wk, Wv, bq, bk, bv,
                                    qh, kh, vh);
    sumv_kernel<<<192, 256>>>(vh);
    attn_kernel<<<dim3(8, 192), 256>>>(qh, kh, vh, ao);
    gemm_o<<<192, 256>>>(ao, Wo, bo, out);
}

// round 17
// speedup vs baseline: 1.5541x; 1.0150x over previous
#include <cuda_runtime.h>
#include <cuda_bf16.h>
#include <cstdint>

// Problem constants
#define R_TOTAL 24576   // B*T*N = 2*12*1024
#define DMODEL  128
#define NKEYS   1024
#define NHEADS  8

// ---------- helpers ----------
__device__ __forceinline__ float ex2(float x) {
    float y; asm("ex2.approx.f32 %0, %1;" : "=f"(y) : "f"(x)); return y;
}
// pack two floats to bf16x2: low half = first arg, high half = second arg
__device__ __forceinline__ uint32_t pkbf(float lo, float hi) {
    uint32_t d;
    asm("cvt.rn.bf16x2.f32 %0, %1, %2;" : "=r"(d) : "f"(hi), "f"(lo));
    return d;
}

// HMMA: mma.sync m16n8k16 bf16 (baseline PTX, works on sm_103)
__device__ __forceinline__ void mma_bf16(float* c, const uint32_t* a,
                                         uint32_t b0, uint32_t b1) {
    asm volatile(
        "mma.sync.aligned.m16n8k16.row.col.f32.bf16.bf16.f32 "
        "{%0,%1,%2,%3}, {%4,%5,%6,%7}, {%8,%9}, {%0,%1,%2,%3};"
        : "+f"(c[0]), "+f"(c[1]), "+f"(c[2]), "+f"(c[3])
        : "r"(a[0]), "r"(a[1]), "r"(a[2]), "r"(a[3]), "r"(b0), "r"(b1));
}

// split fp32 -> (hi, lo) bf16 pair
__device__ __forceinline__ void bsplit(float x, unsigned short& h, unsigned short& l) {
    __nv_bfloat16 bh = __float2bfloat16(x);
    __nv_bfloat16 bl = __float2bfloat16(x - __bfloat162float(bh));
    h = __bfloat16_as_ushort(bh);
    l = __bfloat16_as_ushort(bl);
}

// ---------- scratch (no cudaMalloc allowed) ----------
__device__ float g_qh[R_TOTAL * DMODEL];   // head-major (bt,h,n,hd)
__device__ float g_kh[R_TOTAL * DMODEL];
__device__ float g_vh[R_TOTAL * DMODEL];
__device__ float g_ao[R_TOTAL * DMODEL];   // attention out, row-major (r, d)
__device__ float g_sumv[192 * 16];         // per (bth, hd): sum_n V[n][hd]

// ============================================================================
// HMMA projection GEMM (round-10 PROVEN 3-term version):
// out[r,j] = X[r,:]·W[j,:] + bias[j]; split-bf16 Ahi·Bhi + Ahi·Blo + Alo·Bhi.
// 128x128 tile/CTA, 8 warps 4(m)x2(n).
// ============================================================================
#define SPAD 20

__device__ __forceinline__ void gemm_hmma_body(
    const float* __restrict__ X, const float* __restrict__ W,
    const float* __restrict__ bias, float* __restrict__ out,
    int row0, int headmajor)
{
    __shared__ uint32_t XsHi[128 * SPAD], XsLo[128 * SPAD];
    __shared__ uint32_t WsHi[128 * SPAD], WsLo[128 * SPAD];

    const int tid   = threadIdx.x;
    const int wid   = tid >> 5;
    const int lane  = tid & 31;
    const int g     = lane >> 2;
    const int t     = lane & 3;
    const int mwarp = wid & 3;
    const int nwarp = wid >> 2;

    float c[2][8][4];
    #pragma unroll
    for (int mt = 0; mt < 2; ++mt)
        #pragma unroll
        for (int nt = 0; nt < 8; ++nt)
            #pragma unroll
            for (int e = 0; e < 4; ++e) c[mt][nt][e] = 0.0f;

    for (int chunk = 0; chunk < 4; ++chunk) {
        const int k0 = chunk * 32;
        #pragma unroll
        for (int i = 0; i < 4; ++i) {
            int idx = tid + i * 256;
            int row = idx >> 3;
            int c4  = idx & 7;
            float4 v = *(const float4*)(X + (size_t)(row0 + row) * 128 + k0 + c4 * 4);
            unsigned short h0, l0, h1, l1, h2, l2, h3, l3;
            bsplit(v.x, h0, l0); bsplit(v.y, h1, l1);
            bsplit(v.z, h2, l2); bsplit(v.w, h3, l3);
            int wi = row * SPAD + c4 * 2;
            XsHi[wi]     = (uint32_t)h0 | ((uint32_t)h1 << 16);
            XsHi[wi + 1] = (uint32_t)h2 | ((uint32_t)h3 << 16);
            XsLo[wi]     = (uint32_t)l0 | ((uint32_t)l1 << 16);
            XsLo[wi + 1] = (uint32_t)l2 | ((uint32_t)l3 << 16);

            float4 wv = *(const float4*)(W + (size_t)row * 128 + k0 + c4 * 4);
            bsplit(wv.x, h0, l0); bsplit(wv.y, h1, l1);
            bsplit(wv.z, h2, l2); bsplit(wv.w, h3, l3);
            WsHi[wi]     = (uint32_t)h0 | ((uint32_t)h1 << 16);
            WsHi[wi + 1] = (uint32_t)h2 | ((uint32_t)h3 << 16);
            WsLo[wi]     = (uint32_t)l0 | ((uint32_t)l1 << 16);
            WsLo[wi + 1] = (uint32_t)l2 | ((uint32_t)l3 << 16);
        }
        __syncthreads();

        #pragma unroll
        for (int ks = 0; ks < 2; ++ks) {
            const int kw = ks * 8;
            uint32_t ahi[2][4], alo[2][4];
            #pragma unroll
            for (int mt = 0; mt < 2; ++mt) {
                int r0 = (mwarp * 32 + mt * 16 + g) * SPAD + kw + t;
                int r8 = r0 + 8 * SPAD;
                ahi[mt][0] = XsHi[r0];     ahi[mt][1] = XsHi[r8];
                ahi[mt][2] = XsHi[r0 + 4]; ahi[mt][3] = XsHi[r8 + 4];
                alo[mt][0] = XsLo[r0];     alo[mt][1] = XsLo[r8];
                alo[mt][2] = XsLo[r0 + 4]; alo[mt][3] = XsLo[r8 + 4];
            }
            #pragma unroll
            for (int nt = 0; nt < 8; ++nt) {
                int b = (nwarp * 64 + nt * 8 + g) * SPAD + kw + t;
                uint32_t bh0 = WsHi[b], bh1 = WsHi[b + 4];
                uint32_t bl0 = WsLo[b], bl1 = WsLo[b + 4];
                #pragma unroll
                for (int mt = 0; mt < 2; ++mt) {
                    mma_bf16(c[mt][nt], ahi[mt], bh0, bh1);
                    mma_bf16(c[mt][nt], ahi[mt], bl0, bl1);
                    mma_bf16(c[mt][nt], alo[mt], bh0, bh1);
                }
            }
        }
        __syncthreads();
    }

    #pragma unroll
    for (int mt = 0; mt < 2; ++mt) {
        int rA = row0 + mwarp * 32 + mt * 16 + g;
        int rB = rA + 8;
        #pragma unroll
        for (int nt = 0; nt < 8; ++nt) {
            int j0 = nwarp * 64 + nt * 8 + t * 2;
            float b0 = bias[j0], b1 = bias[j0 + 1];
            float2 oA = { c[mt][nt][0] + b0, c[mt][nt][1] + b1 };
            float2 oB = { c[mt][nt][2] + b0, c[mt][nt][3] + b1 };
            if (headmajor) {
                int h = j0 >> 4, hd = j0 & 15;
                int btA = rA >> 10, nA = rA & 1023;
                int btB = rB >> 10, nB = rB & 1023;
                *(float2*)(out + (((size_t)(btA * NHEADS + h)) << 14) + (nA << 4) + hd) = oA;
                *(float2*)(out + (((size_t)(btB * NHEADS + h)) << 14) + (nB << 4) + hd) = oB;
            } else {
                *(float2*)(out + (size_t)rA * 128 + j0) = oA;
                *(float2*)(out + (size_t)rB * 128 + j0) = oB;
            }
        }
    }
}

__global__ __launch_bounds__(256, 2) void gemm_qkv(
    const float* __restrict__ Xq, const float* __restrict__ Xk,
    const float* __restrict__ Xv,
    const float* __restrict__ Wq, const float* __restrict__ Wk,
    const float* __restrict__ Wv,
    const float* __restrict__ bq, const float* __restrict__ bk,
    const float* __restrict__ bv,
    float* __restrict__ oq, float* __restrict__ ok, float* __restrict__ ov)
{
    const int which = blockIdx.y;
    const float* X = (which == 0) ? Xq : (which == 1) ? Xk : Xv;
    const float* W = (which == 0) ? Wq : (which == 1) ? Wk : Wv;
    const float* b = (which == 0) ? bq : (which == 1) ? bk : bv;
    float*       o = (which == 0) ? oq : (which == 1) ? ok : ov;
    gemm_hmma_body(X, W, b, o, blockIdx.x * 128, 1);
}

__global__ __launch_bounds__(256, 2) void gemm_o(
    const float* __restrict__ X, const float* __restrict__ W,
    const float* __restrict__ bias, float* __restrict__ out)
{
    gemm_hmma_body(X, W, bias, out, blockIdx.x * 128, 0);
}

// ============================================================================
// sumv: g_sumv[bth][hd] = sum over all 1024 keys of V[bth][n][hd] (fp32 exact).
// ============================================================================
__global__ __launch_bounds__(256) void sumv_kernel(const float* __restrict__ Vh)
{
    __shared__ float sm[16][17];
    const int tid = threadIdx.x;
    const int seg = tid >> 4;
    const int hd  = tid & 15;
    const float* Vg = Vh + (size_t)blockIdx.x * 16384;
    float s = 0.0f;
    #pragma unroll 4
    for (int n = 0; n < 64; ++n)
        s += Vg[((seg * 64 + n) << 4) + hd];
    sm[seg][hd] = s;
    __syncthreads();
    if (tid < 16) {
        float tot = 0.0f;
        #pragma unroll
        for (int ss = 0; ss < 16; ++ss) tot += sm[ss][tid];
        g_sumv[blockIdx.x * 16 + tid] = tot;
    }
}

// ============================================================================
// Attention v11: single-mma flash-attention with DOUBLE-BUFFERED K/V smem.
// One __syncthreads per chunk (was 2): stage chunk c+1 into buf^1 from
// prefetched regs, issue LDG for c+2, compute chunk c from buf, sync.
//   S  = Qhi·Khi ; p' = 2^s - 1 ; O = (SumV + P'·Vhi)/(1024 + sum p')
// Grid (8,192); 256 thr / 8 warps; warp owns 16 query rows.
// ============================================================================
#define CK 64
#define NCHUNK (NKEYS / CK)
#define KSTRIDE 12       // words per K row (8 used + 4 pad)
#define VSTRIDE 72       // u16 per Vt row (64 used + 8 pad)

__global__ __launch_bounds__(256, 2) void attn_kernel(
    const float* __restrict__ Qh, const float* __restrict__ Kh,
    const float* __restrict__ Vh, float* __restrict__ Oc)
{
    __shared__ uint32_t Ksm[2][CK * KSTRIDE];
    __shared__ unsigned short Vt[2][16 * VSTRIDE];

    const int tid  = threadIdx.x;
    const int wid  = tid >> 5;
    const int lane = tid & 31;
    const int g    = lane >> 2;
    const int t    = lane & 3;

    const int qt  = blockIdx.x;
    const int bth = blockIdx.y;
    const int bt  = bth >> 3, h = bth & 7;

    const float* Qg = Qh + (size_t)bth * 16384;
    const float* Kg = Kh + (size_t)bth * 16384;
    const float* Vg = Vh + (size_t)bth * 16384;

    // ---- Q fragment (bf16), prescaled by 0.25*log2(e) ----
    const float sc = 0.25f * 1.4426950408889634f;
    const int rA = qt * 128 + wid * 16 + g;
    const int rB = rA + 8;
    uint32_t aq[4];
    {
        float2 xA0 = *(const float2*)(Qg + rA * 16 + 2 * t);
        float2 xB0 = *(const float2*)(Qg + rB * 16 + 2 * t);
        float2 xA1 = *(const float2*)(Qg + rA * 16 + 2 * t + 8);
        float2 xB1 = *(const float2*)(Qg + rB * 16 + 2 * t + 8);
        aq[0] = pkbf(xA0.x * sc, xA0.y * sc);
        aq[1] = pkbf(xB0.x * sc, xB0.y * sc);
        aq[2] = pkbf(xA1.x * sc, xA1.y * sc);
        aq[3] = pkbf(xB1.x * sc, xB1.y * sc);
    }

    float o[2][4];
    #pragma unroll
    for (int j = 0; j < 2; ++j)
        #pragma unroll
        for (int e = 0; e < 4; ++e) o[j][e] = 0.0f;
    float rsA = 0.0f, rsB = 0.0f;   // accumulate p' = p - 1

    // staging roles: thread -> one float4 of K and one of V per chunk
    const int srow = tid >> 2;       // key row in chunk
    const int sc4  = tid & 3;        // float4 slot
    const int kwi  = srow * KSTRIDE + sc4 * 2;

    // ---- prologue: stage chunk 0 into buf 0; prefetch chunk 1 ----
    {
        float4 k0 = *(const float4*)(Kg + tid * 4);
        float4 v0 = *(const float4*)(Vg + tid * 4);
        Ksm[0][kwi]     = pkbf(k0.x, k0.y);
        Ksm[0][kwi + 1] = pkbf(k0.z, k0.w);
        #pragma unroll
        for (int e = 0; e < 4; ++e) {
            float ve = (e == 0) ? v0.x : (e == 1) ? v0.y : (e == 2) ? v0.z : v0.w;
            Vt[0][(sc4 * 4 + e) * VSTRIDE + srow] =
                __bfloat16_as_ushort(__float2bfloat16(ve));
        }
    }
    float4 kreg = *(const float4*)(Kg + CK * 16 + tid * 4);
    float4 vreg = *(const float4*)(Vg + CK * 16 + tid * 4);
    __syncthreads();

    #pragma unroll 1
    for (int cix = 0; cix < NCHUNK; ++cix) {
        const int buf = cix & 1;

        // ---- stage chunk cix+1 into buf^1 (regs already loaded) ----
        if (cix + 1 < NCHUNK) {
            Ksm[buf ^ 1][kwi]     = pkbf(kreg.x, kreg.y);
            Ksm[buf ^ 1][kwi + 1] = pkbf(kreg.z, kreg.w);
            #pragma unroll
            for (int e = 0; e < 4; ++e) {
                float ve = (e == 0) ? vreg.x : (e == 1) ? vreg.y
                         : (e == 2) ? vreg.z : vreg.w;
                Vt[buf ^ 1][(sc4 * 4 + e) * VSTRIDE + srow] =
                    __bfloat16_as_ushort(__float2bfloat16(ve));
            }
        }
        // ---- prefetch chunk cix+2 (LDG latency hidden under compute) ----
        if (cix + 2 < NCHUNK) {
            kreg = *(const float4*)(Kg + (cix + 2) * CK * 16 + tid * 4);
            vreg = *(const float4*)(Vg + (cix + 2) * CK * 16 + tid * 4);
        }

        // ---- S = Qhi·Khi (single mma per 8-key tile) ----
        const uint32_t* Kc = Ksm[buf];
        float s[8][4];
        #pragma unroll
        for (int i = 0; i < 8; ++i) {
            s[i][0] = 0.0f; s[i][1] = 0.0f; s[i][2] = 0.0f; s[i][3] = 0.0f;
            int b = (8 * i + g) * KSTRIDE + t;
            mma_bf16(s[i], aq, Kc[b], Kc[b + 4]);
        }

        // ---- centered softmax + PV (single mma per tile) ----
        const uint32_t* VtW = (const uint32_t*)Vt[buf];
        #pragma unroll
        for (int ks = 0; ks < 4; ++ks) {
            uint32_t ap[4];
            #pragma unroll
            for (int half = 0; half < 2; ++half) {
                float* cc = s[2 * ks + half];
                float p0 = ex2(cc[0]) - 1.0f, p1 = ex2(cc[1]) - 1.0f;
                float p2 = ex2(cc[2]) - 1.0f, p3 = ex2(cc[3]) - 1.0f;
                rsA += p0 + p1;
                rsB += p2 + p3;
                ap[2 * half]     = pkbf(p0, p1);
                ap[2 * half + 1] = pkbf(p2, p3);
            }
            #pragma unroll
            for (int j = 0; j < 2; ++j) {
                int b = (8 * j + g) * (VSTRIDE / 2) + 8 * ks + t;
                mma_bf16(o[j], ap, VtW[b], VtW[b + 4]);
            }
        }
        __syncthreads();   // buf^1 staged + all reads of buf done
    }

    // ---- denominators: sum p = 1024 + sum p' ----
    rsA += __shfl_xor_sync(0xffffffffu, rsA, 1);
    rsA += __shfl_xor_sync(0xffffffffu, rsA, 2);
    rsB += __shfl_xor_sync(0xffffffffu, rsB, 1);
    rsB += __shfl_xor_sync(0xffffffffu, rsB, 2);
    const float invA = 1.0f / (1024.0f + rsA);
    const float invB = 1.0f / (1024.0f + rsB);

    // ---- O = (SumV + o) * inv, row-major for gemm_o ----
    const float* sv = g_sumv + bth * 16;
    #pragma unroll
    for (int j = 0; j < 2; ++j) {
        int hc = 8 * j + 2 * t;
        float sv0 = sv[hc], sv1 = sv[hc + 1];
        int col = h * 16 + hc;
        float2 oA = { (sv0 + o[j][0]) * invA, (sv1 + o[j][1]) * invA };
        float2 oB = { (sv0 + o[j][2]) * invB, (sv1 + o[j][3]) * invB };
        *(float2*)(Oc + ((size_t)((bt << 10) | rA)) * 128 + col) = oA;
        *(float2*)(Oc + ((size_t)((bt << 10) | rB)) * 128 + col) = oB;
    }
}

// ============================================================================
extern "C" void kernel_launch(void* const* d_in, const int* in_sizes, int n_in,
                              void* d_out, int out_size) {
    const float* query = (const float*)d_in[0];
    const float* key   = (const float*)d_in[1];
    const float* value = (const float*)d_in[2];
    const float* Wq    = (const float*)d_in[3];
    const float* bq    = (const float*)d_in[4];
    const float* Wk    = (const float*)d_in[5];
    const float* bk    = (const float*)d_in[6];
    const float* Wv    = (const float*)d_in[7];
    const float* bv    = (const float*)d_in[8];
    const float* Wo    = (const float*)d_in[9];
    const float* bo    = (const float*)d_in[10];
    float* out = (float*)d_out;

    float *qh, *kh, *vh, *ao;
    cudaGetSymbolAddress((void**)&qh, g_qh);
    cudaGetSymbolAddress((void**)&kh, g_kh);
    cudaGetSymbolAddress((void**)&vh, g_vh);
    cudaGetSymbolAddress((void**)&ao, g_ao);

    gemm_qkv<<<dim3(192, 3), 256>>>(query, key, value,
                                    Wq, Wk, Wv, bq, bk, bv,
                                    qh, kh, vh);
    sumv_kernel<<<192, 256>>>(vh);
    attn_kernel<<<dim3(8, 192), 256>>>(qh, kh, vh, ao);
    gemm_o<<<192, 256>>>(ao, Wo, bo, out);
}